// round 14
// baseline (speedup 1.0000x reference)
#include <cuda_runtime.h>
#include <cuda_bf16.h>

// out[n,p,:] = feat[n,p,:] * mean_m task[n,m,p]
// n=32, m=16, p=1024, d=512 (fp32)
//
// Champion config (R11) + grid-stride wave smoothing:
//  - float4 feat loads, DEFAULT policy (__ldg); __stcs stores
//  - warp-autonomous 2 rows/warp means via width-16 shfl reduce
//  - NEW: 1024 blocks x 2 tiles (grid-stride) instead of 2048 x 1 —
//    halves dispatch count and smooths the 2.3-wave tail (blocks roll
//    straight into tile 2 instead of waiting on the CLC refill).

#define N_ 32
#define M_ 16
#define P_ 1024
#define D_ 512

#define TPB_ 256
#define ROWS_PER_TILE_ 16   // 8 warps x 2 rows
#define TILES_ ((N_ * P_) / ROWS_PER_TILE_)   // 2048
#define GRID_ (TILES_ / 2)                     // 1024

__global__ __launch_bounds__(TPB_, 8)
void MAP_fused_kernel(const float* __restrict__ task,
                      const float* __restrict__ feat,
                      float* __restrict__ out) {
    const int tid  = threadIdx.x;
    const int warp = tid >> 5;
    const int lane = tid & 31;

    const int m = lane & 15;             // 0..15
    const int dpr = lane >> 4;           // +0 row A lanes, +1 row B lanes

    const float4* f4 = reinterpret_cast<const float4*>(feat);
    float4*       o4 = reinterpret_cast<float4*>(out);

#pragma unroll
    for (int t = 0; t < 2; ++t) {
        const int tile = blockIdx.x + t * GRID_;
        const int rowA = tile * ROWS_PER_TILE_ + warp * 2;   // n*P_ + p
        const int n  = rowA >> 10;
        const int p0 = rowA & (P_ - 1);

        // ---- task load (issued first: feeds the shuffle chain) ----
        float tv = __ldg(task + (size_t)n * (M_ * P_) + m * P_ + (p0 + dpr));

        // ---- feat loads (default policy; overlap task latency) ----
        const size_t a = (size_t)rowA * (D_ / 4) + lane;     // row A, this lane
        float4 va[4], vb[4];
#pragma unroll
        for (int j = 0; j < 4; ++j)
            va[j] = __ldg(f4 + a + j * 32);
#pragma unroll
        for (int j = 0; j < 4; ++j)
            vb[j] = __ldg(f4 + a + (D_ / 4) + j * 32);

        // ---- segment reduce (width 16) -> both row means ----
        tv += __shfl_xor_sync(0xffffffffu, tv, 8, 16);
        tv += __shfl_xor_sync(0xffffffffu, tv, 4, 16);
        tv += __shfl_xor_sync(0xffffffffu, tv, 2, 16);
        tv += __shfl_xor_sync(0xffffffffu, tv, 1, 16);
        const float muA = __shfl_sync(0xffffffffu, tv, 0)  * (1.0f / (float)M_);
        const float muB = __shfl_sync(0xffffffffu, tv, 16) * (1.0f / (float)M_);

        // ---- scale + store (evict-first) ----
#pragma unroll
        for (int j = 0; j < 4; ++j) {
            float4 r;
            r.x = va[j].x * muA; r.y = va[j].y * muA;
            r.z = va[j].z * muA; r.w = va[j].w * muA;
            __stcs(o4 + a + j * 32, r);
        }
#pragma unroll
        for (int j = 0; j < 4; ++j) {
            float4 r;
            r.x = vb[j].x * muB; r.y = vb[j].y * muB;
            r.z = vb[j].z * muB; r.w = vb[j].w * muB;
            __stcs(o4 + a + (D_ / 4) + j * 32, r);
        }
    }
}

extern "C" void kernel_launch(void* const* d_in, const int* in_sizes, int n_in,
                              void* d_out, int out_size) {
    const float* task = (const float*)d_in[0];   // [32,16,1024]
    const float* feat = (const float*)d_in[1];   // [32,1024,512]
    float* out = (float*)d_out;                  // [32,1024,512]
    (void)in_sizes; (void)n_in; (void)out_size;

    MAP_fused_kernel<<<GRID_, TPB_>>>(task, feat, out);
}